// round 3
// baseline (speedup 1.0000x reference)
#include <cuda_runtime.h>
#include <math.h>

// ---------------------------------------------------------------------------
// RandomProjection: out[b,o] = mean_s( cos(x[b,s,:], p[o,:]) )
//   m[b,:] = mean_s( x[b,s,:] / max(||x[b,s]||, eps) )      (kernel 1, partials)
//   out[b,o] = (m[b,:] . p[o,:]) / max(||p[o]||, eps)       (kernel 2)
// ---------------------------------------------------------------------------

#define B_   32
#define S_   512
#define D_   768
#define O_   2048
#define EPS_ 1e-8f
#define PQ_  4            // partials per batch (s split in 4 quarters)

// race-free partials: [PQ][B][D]; fully overwritten every call
__device__ float g_part[PQ_ * B_ * D_];

// ---- packed f32x2 helpers --------------------------------------------------
__device__ __forceinline__ void fma2(unsigned long long& d,
                                     unsigned long long a,
                                     unsigned long long b) {
    asm("fma.rn.f32x2 %0, %1, %2, %3;" : "=l"(d) : "l"(a), "l"(b), "l"(d));
}
__device__ __forceinline__ float unpack_sum(unsigned long long v) {
    float lo, hi;
    asm("mov.b64 {%0, %1}, %2;" : "=f"(lo), "=f"(hi) : "l"(v));
    return lo + hi;
}

// ---------------------------------------------------------------------------
// Kernel 1: per-row normalize + partial sequence-mean. (L2-roofline bound)
// Grid: 128 blocks = (b, quarter q). Block: 512 threads = 16 warps.
// ---------------------------------------------------------------------------
__global__ void __launch_bounds__(512, 1)
reduce_x_kernel(const float* __restrict__ x) {
    __shared__ float4 sm[16 * 192];   // 48 KB

    const int q    = blockIdx.x & 3;
    const int b    = blockIdx.x >> 2;
    const int warp = threadIdx.x >> 5;
    const int lane = threadIdx.x & 31;

    const float4* base = reinterpret_cast<const float4*>(
        x + ((size_t)b * S_ + (size_t)q * 128 + (size_t)warp * 8) * D_);

    const float inv_S = 1.0f / (float)S_;

    float4 acc[6];
    #pragma unroll
    for (int c = 0; c < 6; c++) acc[c] = make_float4(0.f, 0.f, 0.f, 0.f);

    float4 v[6];
    #pragma unroll
    for (int c = 0; c < 6; c++) v[c] = base[lane + 32 * c];

    #pragma unroll
    for (int r = 0; r < 8; r++) {
        float4 vn[6];
        if (r < 7) {
            #pragma unroll
            for (int c = 0; c < 6; c++)
                vn[c] = base[(r + 1) * 192 + lane + 32 * c];
        }

        float ss = 0.f;
        #pragma unroll
        for (int c = 0; c < 6; c++)
            ss += v[c].x * v[c].x + v[c].y * v[c].y
                + v[c].z * v[c].z + v[c].w * v[c].w;
        #pragma unroll
        for (int off = 16; off > 0; off >>= 1)
            ss += __shfl_xor_sync(0xFFFFFFFFu, ss, off);

        const float scale = inv_S / fmaxf(sqrtf(ss), EPS_);

        #pragma unroll
        for (int c = 0; c < 6; c++) {
            acc[c].x += v[c].x * scale;
            acc[c].y += v[c].y * scale;
            acc[c].z += v[c].z * scale;
            acc[c].w += v[c].w * scale;
        }

        if (r < 7) {
            #pragma unroll
            for (int c = 0; c < 6; c++) v[c] = vn[c];
        }
    }

    #pragma unroll
    for (int c = 0; c < 6; c++)
        sm[warp * 192 + lane + 32 * c] = acc[c];
    __syncthreads();

    if (threadIdx.x < 192) {
        float4 s = sm[threadIdx.x];
        #pragma unroll
        for (int w = 1; w < 16; w++) {
            const float4 t = sm[w * 192 + threadIdx.x];
            s.x += t.x; s.y += t.y; s.z += t.z; s.w += t.w;
        }
        reinterpret_cast<float4*>(g_part)[((q * B_ + b) * 192) + threadIdx.x] = s;
    }
}

// ---------------------------------------------------------------------------
// Kernel 2: out[b,o] = (m[b,:] . p[o,:]) / max(||p[o]||, eps)
// Grid: 128 blocks = (b-group bg of 8) x (o-group og of 64). 256 threads.
// Staging: sum 4 partials for the 8 b-rows -> 24 KB smem.
// Warp: 8 consecutive o-rows, processed 2 at a time; inner loop over 8 b with
// packed fma.rn.f32x2 (each LDS.128 feeds 4 f32x2 FMAs = 8 flops*lanes).
// ---------------------------------------------------------------------------
#define BB_ 8
#define OBG 64

__global__ void __launch_bounds__(256, 1)
gemm_kernel(const float* __restrict__ p, float* __restrict__ out) {
    __shared__ float ms[BB_ * D_];   // 24 KB

    const int bg = blockIdx.x & 3;          // b-group (4)
    const int og = blockIdx.x >> 2;         // o-group (32)

    // stage: ms[row][:] = sum_q g_part[q][bg*8+row][:]
    {
        const float4* gp = reinterpret_cast<const float4*>(g_part);
        float4*      dst = reinterpret_cast<float4*>(ms);
        for (int i = threadIdx.x; i < BB_ * 192; i += 256) {
            const int row = i / 192;
            const int idx = i - row * 192;
            const int gb  = bg * BB_ + row;
            float4 a = gp[(0 * B_ + gb) * 192 + idx];
            const float4 b4 = gp[(1 * B_ + gb) * 192 + idx];
            const float4 c4 = gp[(2 * B_ + gb) * 192 + idx];
            const float4 d4 = gp[(3 * B_ + gb) * 192 + idx];
            a.x += b4.x + c4.x + d4.x;
            a.y += b4.y + c4.y + d4.y;
            a.z += b4.z + c4.z + d4.z;
            a.w += b4.w + c4.w + d4.w;
            dst[i] = a;
        }
    }
    __syncthreads();

    const int warp = threadIdx.x >> 5;
    const int lane = threadIdx.x & 31;
    const int o_base = og * OBG + warp * 8;   // 8 o-rows per warp

    #pragma unroll 1
    for (int it = 0; it < 4; it++) {
        const int o0 = o_base + it * 2;

        const ulonglong2* p0 = reinterpret_cast<const ulonglong2*>(
            p + (size_t)o0 * D_);
        const ulonglong2* p1 = reinterpret_cast<const ulonglong2*>(
            p + (size_t)(o0 + 1) * D_);

        ulonglong2 pv0[6], pv1[6];
        #pragma unroll
        for (int c = 0; c < 6; c++) {
            pv0[c] = p0[lane + 32 * c];
            pv1[c] = p1[lane + 32 * c];
        }

        // norms via packed squares
        unsigned long long ss0 = 0ull, ss1 = 0ull;
        #pragma unroll
        for (int c = 0; c < 6; c++) {
            fma2(ss0, pv0[c].x, pv0[c].x);
            fma2(ss0, pv0[c].y, pv0[c].y);
            fma2(ss1, pv1[c].x, pv1[c].x);
            fma2(ss1, pv1[c].y, pv1[c].y);
        }
        float n0 = unpack_sum(ss0);
        float n1 = unpack_sum(ss1);
        #pragma unroll
        for (int off = 16; off > 0; off >>= 1) {
            n0 += __shfl_xor_sync(0xFFFFFFFFu, n0, off);
            n1 += __shfl_xor_sync(0xFFFFFFFFu, n1, off);
        }
        const float rn0 = 1.0f / fmaxf(sqrtf(n0), EPS_);
        const float rn1 = 1.0f / fmaxf(sqrtf(n1), EPS_);

        unsigned long long acc0[BB_], acc1[BB_];
        #pragma unroll
        for (int b = 0; b < BB_; b++) { acc0[b] = 0ull; acc1[b] = 0ull; }

        #pragma unroll
        for (int b = 0; b < BB_; b++) {
            const ulonglong2* mb = reinterpret_cast<const ulonglong2*>(ms + b * D_);
            #pragma unroll
            for (int c = 0; c < 6; c++) {
                const ulonglong2 mv = mb[lane + 32 * c];
                fma2(acc0[b], mv.x, pv0[c].x);
                fma2(acc0[b], mv.y, pv0[c].y);
                fma2(acc1[b], mv.x, pv1[c].x);
                fma2(acc1[b], mv.y, pv1[c].y);
            }
        }

        // reduce 16 scalars across lanes; lane b writes b's two outputs
        #pragma unroll
        for (int b = 0; b < BB_; b++) {
            float a0 = unpack_sum(acc0[b]);
            float a1 = unpack_sum(acc1[b]);
            #pragma unroll
            for (int off = 16; off > 0; off >>= 1) {
                a0 += __shfl_xor_sync(0xFFFFFFFFu, a0, off);
                a1 += __shfl_xor_sync(0xFFFFFFFFu, a1, off);
            }
            if (lane == b) {
                float* orow = out + (size_t)(bg * BB_ + b) * O_;
                orow[o0]     = a0 * rn0;
                orow[o0 + 1] = a1 * rn1;
            }
        }
    }
}

// ---------------------------------------------------------------------------
extern "C" void kernel_launch(void* const* d_in, const int* in_sizes, int n_in,
                              void* d_out, int out_size) {
    const float* x = (const float*)d_in[0];   // [32, 512, 768]
    const float* p = (const float*)d_in[1];   // [2048, 768]
    float*     out = (float*)d_out;           // [32, 2048]

    (void)in_sizes; (void)n_in; (void)out_size;

    // Kernel 1: x -> 4 race-free partials of m
    reduce_x_kernel<<<B_ * PQ_, 512>>>(x);

    // Kernel 2: combine partials + projected GEMM (4 b-groups x 32 o-groups)
    gemm_kernel<<<4 * (O_ / OBG), 256>>>(p, out);
}